// round 3
// baseline (speedup 1.0000x reference)
#include <cuda_runtime.h>
#include <cuda_bf16.h>
#include <math.h>

#define BDIM  8
#define LQ    2048
#define LKV   512
#define HDIM  1024
#define NH    16
#define DH    64

// ---------------- scratch (device globals: allocation-guard-safe) ----------
__device__ float g_ss_q [BDIM * 2 * HDIM];
__device__ float g_ss_kv[BDIM * 2 * HDIM];
__device__ float g_xq_ln [BDIM * LQ  * HDIM];
__device__ float g_xkv_ln[BDIM * LKV * HDIM];
__device__ float g_q    [BDIM * LQ  * HDIM];
__device__ float g_kv   [BDIM * LKV * 2 * HDIM];
__device__ float g_attn [BDIM * LQ  * HDIM];

// ---------------- helpers ---------------------------------------------------
__device__ __forceinline__ unsigned f2tf(float f) {
    unsigned u;
    asm("cvt.rna.tf32.f32 %0, %1;" : "=r"(u) : "f"(f));
    return u;
}

__device__ __forceinline__ void mma_tf32(float* d, const unsigned* a, const unsigned* b) {
    asm volatile(
        "mma.sync.aligned.m16n8k8.row.col.f32.tf32.tf32.f32 "
        "{%0,%1,%2,%3}, {%4,%5,%6,%7}, {%8,%9}, {%0,%1,%2,%3};\n"
        : "+f"(d[0]), "+f"(d[1]), "+f"(d[2]), "+f"(d[3])
        : "r"(a[0]), "r"(a[1]), "r"(a[2]), "r"(a[3]),
          "r"(b[0]), "r"(b[1]));
}

// ---------------- ss = silu(t) @ Wss + bss  (out: [B, 2H]) ------------------
__global__ void __launch_bounds__(256) ss_kernel(
    const float* __restrict__ t, const float* __restrict__ W,
    const float* __restrict__ bsv, float* __restrict__ outp)
{
    __shared__ float st[HDIM];
    int b = blockIdx.y;
    for (int i = threadIdx.x; i < HDIM; i += 256) {
        float x = t[b * HDIM + i];
        st[i] = x / (1.f + __expf(-x));
    }
    __syncthreads();
    int j = blockIdx.x * 256 + threadIdx.x;
    float acc = bsv[j];
#pragma unroll 4
    for (int i = 0; i < HDIM; i++)
        acc = fmaf(st[i], W[(size_t)i * (2 * HDIM) + j], acc);
    outp[b * 2 * HDIM + j] = acc;
}

// ---------------- AdaLN: one block per row ---------------------------------
__global__ void __launch_bounds__(256) adaln_kernel(
    const float* __restrict__ x, const float* __restrict__ ss,
    float* __restrict__ out, int L)
{
    int row = blockIdx.x;
    int b = row / L;
    const float* xr = x + (size_t)row * HDIM;
    int t = threadIdx.x;
    float v[4];
    float s0 = 0.f, s1 = 0.f;
#pragma unroll
    for (int i = 0; i < 4; i++) {
        v[i] = xr[t + i * 256];
        s0 += v[i];
        s1 = fmaf(v[i], v[i], s1);
    }
#pragma unroll
    for (int o = 16; o; o >>= 1) {
        s0 += __shfl_xor_sync(0xffffffffu, s0, o);
        s1 += __shfl_xor_sync(0xffffffffu, s1, o);
    }
    __shared__ float rs0[8], rs1[8];
    int w = t >> 5;
    if ((t & 31) == 0) { rs0[w] = s0; rs1[w] = s1; }
    __syncthreads();
    float ts0 = 0.f, ts1 = 0.f;
#pragma unroll
    for (int i = 0; i < 8; i++) { ts0 += rs0[i]; ts1 += rs1[i]; }
    float mu   = ts0 * (1.f / HDIM);
    float var  = ts1 * (1.f / HDIM) - mu * mu;
    float rstd = rsqrtf(var + 1e-5f);
    const float* sc = ss + (size_t)b * 2 * HDIM;
#pragma unroll
    for (int i = 0; i < 4; i++) {
        int j = t + i * 256;
        float hh = (v[i] - mu) * rstd;
        out[(size_t)row * HDIM + j] = fmaf(sc[j], hh, hh) + sc[HDIM + j];
    }
}

// ---------------- tf32 tensor-core GEMM: C = A @ W + bias (+resid) ---------
// A: [M,K] row-major fp32, W: [K,N] row-major fp32.
// Block tile 128x128x32, 256 threads, 8 warps (4 along M x 2 along N),
// warp tile 32x64 = 2x8 m16n8k8 MMAs per k8-step.
#define GBM 128
#define GBN 128
#define GBK 32

template <bool RESID>
__global__ void __launch_bounds__(256, 2) gemm_tf32_kernel(
    const float* __restrict__ A, const float* __restrict__ W,
    const float* __restrict__ bias, const float* __restrict__ resid,
    float* __restrict__ C, int M, int N, int K)
{
    __shared__ unsigned As[GBM][GBK + 4];   // 128 x 36
    __shared__ unsigned Bs[GBK][GBN + 4];   // 32 x 132

    int tid  = threadIdx.x;
    int warp = tid >> 5, lane = tid & 31;
    int wm = warp >> 1, wn = warp & 1;
    int g  = lane >> 2, tg = lane & 3;
    int m0 = blockIdx.y * GBM;
    int n0 = blockIdx.x * GBN;

    float acc[2][8][4];
#pragma unroll
    for (int mt = 0; mt < 2; mt++)
#pragma unroll
        for (int nt = 0; nt < 8; nt++)
#pragma unroll
            for (int i = 0; i < 4; i++) acc[mt][nt][i] = 0.f;

    int ar = tid >> 3;           // 0..31
    int ac = (tid & 7) * 4;      // 0..28
    int brr = tid >> 5;          // 0..7
    int bcc = (tid & 31) * 4;    // 0..124

    for (int kt = 0; kt < K; kt += GBK) {
        // stage A tile (convert to tf32 once)
#pragma unroll
        for (int i = 0; i < 4; i++) {
            int r = ar + i * 32;
            float4 v = *(const float4*)(A + (size_t)(m0 + r) * K + kt + ac);
            *(uint4*)&As[r][ac] =
                make_uint4(f2tf(v.x), f2tf(v.y), f2tf(v.z), f2tf(v.w));
        }
        // stage B tile
#pragma unroll
        for (int i = 0; i < 4; i++) {
            int r = brr + i * 8;
            float4 v = *(const float4*)(W + (size_t)(kt + r) * N + n0 + bcc);
            *(uint4*)&Bs[r][bcc] =
                make_uint4(f2tf(v.x), f2tf(v.y), f2tf(v.z), f2tf(v.w));
        }
        __syncthreads();

#pragma unroll
        for (int s = 0; s < GBK; s += 8) {
            unsigned a[2][4], bb[8][2];
#pragma unroll
            for (int mt = 0; mt < 2; mt++) {
                int r = wm * 32 + mt * 16;
                a[mt][0] = As[r + g][s + tg];
                a[mt][1] = As[r + g + 8][s + tg];
                a[mt][2] = As[r + g][s + tg + 4];
                a[mt][3] = As[r + g + 8][s + tg + 4];
            }
#pragma unroll
            for (int nt = 0; nt < 8; nt++) {
                int c = wn * 64 + nt * 8 + g;
                bb[nt][0] = Bs[s + tg][c];
                bb[nt][1] = Bs[s + tg + 4][c];
            }
#pragma unroll
            for (int mt = 0; mt < 2; mt++)
#pragma unroll
                for (int nt = 0; nt < 8; nt++)
                    mma_tf32(acc[mt][nt], a[mt], bb[nt]);
        }
        __syncthreads();
    }

    // epilogue: + bias (+ residual)
#pragma unroll
    for (int mt = 0; mt < 2; mt++) {
#pragma unroll
        for (int nt = 0; nt < 8; nt++) {
            int col = n0 + wn * 64 + nt * 8 + 2 * tg;
            float b0 = bias[col], b1 = bias[col + 1];
#pragma unroll
            for (int hr = 0; hr < 2; hr++) {
                int row = m0 + wm * 32 + mt * 16 + g + hr * 8;
                size_t off = (size_t)row * N + col;
                float v0 = acc[mt][nt][hr * 2 + 0] + b0;
                float v1 = acc[mt][nt][hr * 2 + 1] + b1;
                if (RESID) { v0 += resid[off]; v1 += resid[off + 1]; }
                C[off]     = v0;
                C[off + 1] = v1;
            }
        }
    }
}

// ---------------- flash attention (online softmax, tf32 MMA) ---------------
// grid (Lq/64, NH, B), 128 threads (4 warps, 16 q-rows each).
// smem: Qs/Ks/Vs 64x65 tf32, Ss 64x66 f32 (reused as P tf32), stats 3x64.
#define ATTN_SMEM_BYTES ((3 * 64 * 65 + 64 * 66 + 3 * 64) * 4)

__global__ void __launch_bounds__(128) attn_kernel(
    const float* __restrict__ qg, const float* __restrict__ kvg,
    float* __restrict__ og)
{
    extern __shared__ char sm_raw[];
    unsigned* Qs = (unsigned*)sm_raw;       // 64*65
    unsigned* Ks = Qs + 64 * 65;
    unsigned* Vs = Ks + 64 * 65;
    float* Ss  = (float*)(Vs + 64 * 65);    // 64*66
    float* m_s = Ss + 64 * 66;
    float* l_s = m_s + 64;
    float* c_s = l_s + 64;

    int tid = threadIdx.x;
    int warp = tid >> 5, lane = tid & 31;
    int g = lane >> 2, tg = lane & 3;
    int l0 = blockIdx.x * 64;
    int h  = blockIdx.y;
    int b  = blockIdx.z;

    const float* qbase = qg  + ((size_t)(b * LQ  + l0)) * HDIM + h * DH;
    const float* kbase = kvg + ((size_t)(b * LKV)) * (2 * HDIM) + h * DH;
    const float* vbase = kbase + HDIM;

    // stage Q (tf32)
    for (int idx = tid; idx < 64 * 64; idx += 128) {
        int r = idx >> 6, c = idx & 63;
        Qs[r * 65 + c] = f2tf(qbase[(size_t)r * HDIM + c]);
    }
    if (tid < 64) { m_s[tid] = -3.0e38f; l_s[tid] = 0.f; }

    float o[8][4];
#pragma unroll
    for (int nt = 0; nt < 8; nt++)
#pragma unroll
        for (int i = 0; i < 4; i++) o[nt][i] = 0.f;

    int r0 = warp * 16;
    __syncthreads();

    for (int j = 0; j < LKV; j += 64) {
        // stage K and V tiles (tf32)
        for (int idx = tid; idx < 64 * 64; idx += 128) {
            int r = idx >> 6, c = idx & 63;
            size_t go = (size_t)(j + r) * (2 * HDIM) + c;
            Ks[r * 65 + c] = f2tf(kbase[go]);
            Vs[r * 65 + c] = f2tf(vbase[go]);
        }
        __syncthreads();

        // S = Q @ K^T  (warp: 16 rows x 64 kv-cols)
        float sfr[8][4];
#pragma unroll
        for (int nt = 0; nt < 8; nt++)
#pragma unroll
            for (int i = 0; i < 4; i++) sfr[nt][i] = 0.f;

#pragma unroll
        for (int kk = 0; kk < 64; kk += 8) {
            unsigned a[4];
            a[0] = Qs[(r0 + g) * 65 + kk + tg];
            a[1] = Qs[(r0 + g + 8) * 65 + kk + tg];
            a[2] = Qs[(r0 + g) * 65 + kk + tg + 4];
            a[3] = Qs[(r0 + g + 8) * 65 + kk + tg + 4];
#pragma unroll
            for (int nt = 0; nt < 8; nt++) {
                unsigned bb[2];
                bb[0] = Ks[(nt * 8 + g) * 65 + kk + tg];
                bb[1] = Ks[(nt * 8 + g) * 65 + kk + tg + 4];
                mma_tf32(sfr[nt], a, bb);
            }
        }
        // write scaled scores
#pragma unroll
        for (int nt = 0; nt < 8; nt++) {
            int c = nt * 8 + 2 * tg;
            Ss[(r0 + g) * 66 + c]     = sfr[nt][0] * 0.125f;
            Ss[(r0 + g) * 66 + c + 1] = sfr[nt][1] * 0.125f;
            Ss[(r0 + g + 8) * 66 + c]     = sfr[nt][2] * 0.125f;
            Ss[(r0 + g + 8) * 66 + c + 1] = sfr[nt][3] * 0.125f;
        }
        __syncthreads();

        // online softmax: 2 threads per row
        {
            int row = tid >> 1, half = tid & 1;
            float* srow = Ss + row * 66 + half * 32;
            float mx = -3.0e38f;
#pragma unroll
            for (int c2 = 0; c2 < 32; c2++) mx = fmaxf(mx, srow[c2]);
            mx = fmaxf(mx, __shfl_xor_sync(0xffffffffu, mx, 1));
            float mo = m_s[row];
            float mn = fmaxf(mo, mx);
            float sum = 0.f;
#pragma unroll
            for (int c2 = 0; c2 < 32; c2++) {
                float p = __expf(srow[c2] - mn);
                sum += p;
                ((unsigned*)srow)[c2] = f2tf(p);   // P in tf32, RNA (unbiased)
            }
            sum += __shfl_xor_sync(0xffffffffu, sum, 1);
            if (half == 0) {
                float corr = __expf(mo - mn);
                c_s[row] = corr;
                m_s[row] = mn;
                l_s[row] = l_s[row] * corr + sum;
            }
        }
        __syncthreads();

        // rescale O, then O += P @ V
        float c0f = c_s[r0 + g], c1f = c_s[r0 + g + 8];
        unsigned* Ps = (unsigned*)Ss;
#pragma unroll
        for (int nt = 0; nt < 8; nt++) {
            o[nt][0] *= c0f; o[nt][1] *= c0f;
            o[nt][2] *= c1f; o[nt][3] *= c1f;
        }
#pragma unroll
        for (int kk = 0; kk < 64; kk += 8) {
            unsigned a[4];
            a[0] = Ps[(r0 + g) * 66 + kk + tg];
            a[1] = Ps[(r0 + g + 8) * 66 + kk + tg];
            a[2] = Ps[(r0 + g) * 66 + kk + tg + 4];
            a[3] = Ps[(r0 + g + 8) * 66 + kk + tg + 4];
#pragma unroll
            for (int nt = 0; nt < 8; nt++) {
                unsigned bb[2];
                bb[0] = Vs[(kk + tg) * 65 + nt * 8 + g];
                bb[1] = Vs[(kk + tg + 4) * 65 + nt * 8 + g];
                mma_tf32(o[nt], a, bb);
            }
        }
        __syncthreads();
    }

    // finalize: O /= l, store
    float inv0 = 1.f / l_s[r0 + g];
    float inv1 = 1.f / l_s[r0 + g + 8];
    float* ob = og + ((size_t)(b * LQ + l0)) * HDIM + h * DH;
#pragma unroll
    for (int nt = 0; nt < 8; nt++) {
        int c = nt * 8 + 2 * tg;
        size_t off0 = (size_t)(r0 + g) * HDIM + c;
        size_t off1 = (size_t)(r0 + g + 8) * HDIM + c;
        ob[off0]     = o[nt][0] * inv0;
        ob[off0 + 1] = o[nt][1] * inv0;
        ob[off1]     = o[nt][2] * inv1;
        ob[off1 + 1] = o[nt][3] * inv1;
    }
}

// ---------------- host launcher --------------------------------------------
extern "C" void kernel_launch(void* const* d_in, const int* in_sizes, int n_in,
                              void* d_out, int out_size)
{
    const float* x_q    = (const float*)d_in[0];
    const float* x_kv   = (const float*)d_in[1];
    const float* t_vec  = (const float*)d_in[2];
    const float* Wq     = (const float*)d_in[3];
    const float* bq     = (const float*)d_in[4];
    const float* Wkv    = (const float*)d_in[5];
    const float* bkv    = (const float*)d_in[6];
    const float* Wp     = (const float*)d_in[7];
    const float* bp     = (const float*)d_in[8];
    const float* Wss_q  = (const float*)d_in[9];
    const float* bss_q  = (const float*)d_in[10];
    const float* Wss_kv = (const float*)d_in[11];
    const float* bss_kv = (const float*)d_in[12];
    float* out = (float*)d_out;

    float *ss_q, *ss_kv, *xq_ln, *xkv_ln, *qb, *kvb, *attnb;
    cudaGetSymbolAddress((void**)&ss_q,   g_ss_q);
    cudaGetSymbolAddress((void**)&ss_kv,  g_ss_kv);
    cudaGetSymbolAddress((void**)&xq_ln,  g_xq_ln);
    cudaGetSymbolAddress((void**)&xkv_ln, g_xkv_ln);
    cudaGetSymbolAddress((void**)&qb,     g_q);
    cudaGetSymbolAddress((void**)&kvb,    g_kv);
    cudaGetSymbolAddress((void**)&attnb,  g_attn);

    // 1) adaLN scale/shift vectors
    ss_kernel<<<dim3(2 * HDIM / 256, BDIM), 256>>>(t_vec, Wss_q,  bss_q,  ss_q);
    ss_kernel<<<dim3(2 * HDIM / 256, BDIM), 256>>>(t_vec, Wss_kv, bss_kv, ss_kv);

    // 2) adaLN
    adaln_kernel<<<BDIM * LQ,  256>>>(x_q,  ss_q,  xq_ln,  LQ);
    adaln_kernel<<<BDIM * LKV, 256>>>(x_kv, ss_kv, xkv_ln, LKV);

    // 3) projections
    gemm_tf32_kernel<false><<<dim3(HDIM / GBN, BDIM * LQ / GBM), 256>>>(
        xq_ln, Wq, bq, nullptr, qb, BDIM * LQ, HDIM, HDIM);
    gemm_tf32_kernel<false><<<dim3(2 * HDIM / GBN, BDIM * LKV / GBM), 256>>>(
        xkv_ln, Wkv, bkv, nullptr, kvb, BDIM * LKV, 2 * HDIM, HDIM);

    // 4) attention
    cudaFuncSetAttribute(attn_kernel,
                         cudaFuncAttributeMaxDynamicSharedMemorySize,
                         ATTN_SMEM_BYTES);
    attn_kernel<<<dim3(LQ / 64, NH, BDIM), 128, ATTN_SMEM_BYTES>>>(qb, kvb, attnb);

    // 5) output projection + residual
    gemm_tf32_kernel<true><<<dim3(HDIM / GBN, BDIM * LQ / GBM), 256>>>(
        attnb, Wp, bp, x_q, out, BDIM * LQ, HDIM, HDIM);
}

// round 4
// speedup vs baseline: 2.0663x; 2.0663x over previous
#include <cuda_runtime.h>
#include <cuda_bf16.h>
#include <math.h>

#define BDIM  8
#define LQ    2048
#define LKV   512
#define HDIM  1024
#define NH    16
#define DH    64

// ---------------- scratch (device globals: allocation-guard-safe) ----------
__device__ float g_ss_q [BDIM * 2 * HDIM];
__device__ float g_ss_kv[BDIM * 2 * HDIM];
__device__ float g_xq_ln [BDIM * LQ  * HDIM];
__device__ float g_xkv_ln[BDIM * LKV * HDIM];
__device__ float g_q    [BDIM * LQ  * HDIM];
__device__ float g_kv   [BDIM * LKV * 2 * HDIM];
__device__ float g_attn [BDIM * LQ  * HDIM];
__device__ float g_wq  [HDIM * HDIM];
__device__ float g_wkv [HDIM * 2 * HDIM];
__device__ float g_wp  [HDIM * HDIM];

// ---------------- helpers ---------------------------------------------------
__device__ __forceinline__ unsigned f2tf(float f) {
    unsigned u;
    asm("cvt.rna.tf32.f32 %0, %1;" : "=r"(u) : "f"(f));
    return u;
}

__device__ __forceinline__ void mma_tf32(float* d, const unsigned* a, const unsigned* b) {
    asm volatile(
        "mma.sync.aligned.m16n8k8.row.col.f32.tf32.tf32.f32 "
        "{%0,%1,%2,%3}, {%4,%5,%6,%7}, {%8,%9}, {%0,%1,%2,%3};\n"
        : "+f"(d[0]), "+f"(d[1]), "+f"(d[2]), "+f"(d[3])
        : "r"(a[0]), "r"(a[1]), "r"(a[2]), "r"(a[3]),
          "r"(b[0]), "r"(b[1]));
}

#define CP16(smptr, gptr)                                                     \
    asm volatile("cp.async.cg.shared.global [%0], [%1], 16;\n"                \
                 :: "r"((unsigned)__cvta_generic_to_shared(smptr)), "l"(gptr))
#define CP_COMMIT()  asm volatile("cp.async.commit_group;\n" ::: "memory")
#define CP_WAIT1()   asm volatile("cp.async.wait_group 1;\n" ::: "memory")
#define CP_WAIT0()   asm volatile("cp.async.wait_group 0;\n" ::: "memory")

// ---------------- pre-round weights to tf32 bit patterns -------------------
__global__ void __launch_bounds__(256) round_tf32_kernel(
    const float* __restrict__ in, float* __restrict__ out)
{
    int i = (blockIdx.x * 256 + threadIdx.x) * 4;
    float4 v = *(const float4*)(in + i);
    uint4 u = make_uint4(f2tf(v.x), f2tf(v.y), f2tf(v.z), f2tf(v.w));
    *(uint4*)(out + i) = u;
}

// ---------------- ss = silu(t) @ Wss + bss  (out: [B, 2H]) ------------------
__global__ void __launch_bounds__(256) ss_kernel(
    const float* __restrict__ t, const float* __restrict__ W,
    const float* __restrict__ bsv, float* __restrict__ outp)
{
    __shared__ float st[HDIM];
    int b = blockIdx.y;
    for (int i = threadIdx.x; i < HDIM; i += 256) {
        float x = t[b * HDIM + i];
        st[i] = x / (1.f + __expf(-x));
    }
    __syncthreads();
    int j = blockIdx.x * 256 + threadIdx.x;
    float acc = bsv[j];
#pragma unroll 4
    for (int i = 0; i < HDIM; i++)
        acc = fmaf(st[i], W[(size_t)i * (2 * HDIM) + j], acc);
    outp[b * 2 * HDIM + j] = acc;
}

// ---------------- AdaLN: one block per row, tf32-rounded output ------------
__global__ void __launch_bounds__(256) adaln_kernel(
    const float* __restrict__ x, const float* __restrict__ ss,
    float* __restrict__ out, int L)
{
    int row = blockIdx.x;
    int b = row / L;
    const float* xr = x + (size_t)row * HDIM;
    int t = threadIdx.x;
    float4 v = *(const float4*)(xr + t * 4);
    float s0 = v.x + v.y + v.z + v.w;
    float s1 = v.x * v.x + v.y * v.y + v.z * v.z + v.w * v.w;
#pragma unroll
    for (int o = 16; o; o >>= 1) {
        s0 += __shfl_xor_sync(0xffffffffu, s0, o);
        s1 += __shfl_xor_sync(0xffffffffu, s1, o);
    }
    __shared__ float rs0[8], rs1[8];
    int w = t >> 5;
    if ((t & 31) == 0) { rs0[w] = s0; rs1[w] = s1; }
    __syncthreads();
    float ts0 = 0.f, ts1 = 0.f;
#pragma unroll
    for (int i = 0; i < 8; i++) { ts0 += rs0[i]; ts1 += rs1[i]; }
    float mu   = ts0 * (1.f / HDIM);
    float var  = ts1 * (1.f / HDIM) - mu * mu;
    float rstd = rsqrtf(var + 1e-5f);
    const float* sc = ss + (size_t)b * 2 * HDIM;
    float4 scv = *(const float4*)(sc + t * 4);
    float4 biv = *(const float4*)(sc + HDIM + t * 4);
    float h0 = (v.x - mu) * rstd, h1 = (v.y - mu) * rstd;
    float h2 = (v.z - mu) * rstd, h3 = (v.w - mu) * rstd;
    uint4 r = make_uint4(
        f2tf(fmaf(scv.x, h0, h0) + biv.x),
        f2tf(fmaf(scv.y, h1, h1) + biv.y),
        f2tf(fmaf(scv.z, h2, h2) + biv.z),
        f2tf(fmaf(scv.w, h3, h3) + biv.w));
    *(uint4*)(out + (size_t)row * HDIM + t * 4) = r;
}

// ---------------- tf32 GEMM, cp.async double-buffered ----------------------
// A: [M,K] row-major fp32 (tf32-rounded bits), W: [K,N] row-major (rounded).
// Block tile 128x128x32, 256 threads, 8 warps (4 M x 2 N), warp 32x64.
#define GBM 128
#define GBN 128
#define GBK 32
#define GEMM_SMEM ((2 * GBM * 36 + 2 * GBK * 132) * 4)

template <bool RESID, bool ROUND>
__global__ void __launch_bounds__(256, 2) gemm_tf32_kernel(
    const float* __restrict__ A, const float* __restrict__ W,
    const float* __restrict__ bias, const float* __restrict__ resid,
    float* __restrict__ C, int M, int N, int K)
{
    extern __shared__ float sm[];
    float* As = sm;                     // [2][128*36]
    float* Bs = sm + 2 * GBM * 36;      // [2][32*132]

    int tid  = threadIdx.x;
    int warp = tid >> 5, lane = tid & 31;
    int wm = warp >> 1, wn = warp & 1;
    int g  = lane >> 2, tg = lane & 3;
    int m0 = blockIdx.y * GBM;
    int n0 = blockIdx.x * GBN;

    float acc[2][8][4] = {};

    int ar  = tid >> 3;          // 0..31
    int ac  = (tid & 7) * 4;     // 0..28
    int brr = tid >> 5;          // 0..7
    int bcc = (tid & 31) * 4;    // 0..124

    const int ntiles = K >> 5;

    // prologue: tile 0 -> buffer 0
    {
#pragma unroll
        for (int i = 0; i < 4; i++) {
            int r = ar + i * 32;
            CP16(&As[r * 36 + ac], A + (size_t)(m0 + r) * K + ac);
        }
#pragma unroll
        for (int i = 0; i < 4; i++) {
            int r = brr + i * 8;
            CP16(&Bs[r * 132 + bcc], W + (size_t)r * N + n0 + bcc);
        }
        CP_COMMIT();
    }

    for (int it = 0; it < ntiles; it++) {
        int buf = it & 1;
        if (it + 1 < ntiles) {
            int kt = (it + 1) << 5;
            float* as = As + (buf ^ 1) * (GBM * 36);
            float* bs = Bs + (buf ^ 1) * (GBK * 132);
#pragma unroll
            for (int i = 0; i < 4; i++) {
                int r = ar + i * 32;
                CP16(&as[r * 36 + ac], A + (size_t)(m0 + r) * K + kt + ac);
            }
#pragma unroll
            for (int i = 0; i < 4; i++) {
                int r = brr + i * 8;
                CP16(&bs[r * 132 + bcc], W + (size_t)(kt + r) * N + n0 + bcc);
            }
            CP_COMMIT();
            CP_WAIT1();
        } else {
            CP_WAIT0();
        }
        __syncthreads();

        const float* as = As + buf * (GBM * 36);
        const float* bs = Bs + buf * (GBK * 132);
#pragma unroll
        for (int s = 0; s < GBK; s += 8) {
            unsigned a[2][4], bb[8][2];
#pragma unroll
            for (int mt = 0; mt < 2; mt++) {
                int r = wm * 32 + mt * 16;
                a[mt][0] = __float_as_uint(as[(r + g)     * 36 + s + tg]);
                a[mt][1] = __float_as_uint(as[(r + g + 8) * 36 + s + tg]);
                a[mt][2] = __float_as_uint(as[(r + g)     * 36 + s + tg + 4]);
                a[mt][3] = __float_as_uint(as[(r + g + 8) * 36 + s + tg + 4]);
            }
#pragma unroll
            for (int nt = 0; nt < 8; nt++) {
                int c = wn * 64 + nt * 8 + g;
                bb[nt][0] = __float_as_uint(bs[(s + tg)     * 132 + c]);
                bb[nt][1] = __float_as_uint(bs[(s + tg + 4) * 132 + c]);
            }
#pragma unroll
            for (int mt = 0; mt < 2; mt++)
#pragma unroll
                for (int nt = 0; nt < 8; nt++)
                    mma_tf32(acc[mt][nt], a[mt], bb[nt]);
        }
        __syncthreads();
    }

    // epilogue: + bias (+ residual) (opt tf32 rounding for MMA consumers)
#pragma unroll
    for (int mt = 0; mt < 2; mt++) {
#pragma unroll
        for (int nt = 0; nt < 8; nt++) {
            int col = n0 + wn * 64 + nt * 8 + 2 * tg;
            float b0 = bias[col], b1 = bias[col + 1];
#pragma unroll
            for (int hr = 0; hr < 2; hr++) {
                int row = m0 + wm * 32 + mt * 16 + g + hr * 8;
                size_t off = (size_t)row * N + col;
                float v0 = acc[mt][nt][hr * 2 + 0] + b0;
                float v1 = acc[mt][nt][hr * 2 + 1] + b1;
                if (RESID) { v0 += resid[off]; v1 += resid[off + 1]; }
                if (ROUND) {
                    C[off]     = __uint_as_float(f2tf(v0));
                    C[off + 1] = __uint_as_float(f2tf(v1));
                } else {
                    C[off]     = v0;
                    C[off + 1] = v1;
                }
            }
        }
    }
}

// ---------------- flash attention, cp.async double-buffered K/V ------------
// grid (Lq/64, NH, B), 128 threads (4 warps, 16 q-rows each).
// q/kv already tf32-rounded. smem: Qs 64x68, Ks/Vs [2]x64x68, Ss 64x68.
#define AP 68
#define ATTN_SMEM ((6 * 64 * AP + 3 * 64) * 4)

__global__ void __launch_bounds__(128) attn_kernel(
    const float* __restrict__ qg, const float* __restrict__ kvg,
    float* __restrict__ og)
{
    extern __shared__ float sm[];
    float* Qs = sm;                    // 64*AP
    float* Ks = Qs + 64 * AP;          // 2 stages
    float* Vs = Ks + 2 * 64 * AP;      // 2 stages
    float* Ss = Vs + 2 * 64 * AP;      // 64*AP
    float* m_s = Ss + 64 * AP;
    float* l_s = m_s + 64;
    float* c_s = l_s + 64;

    int tid = threadIdx.x;
    int warp = tid >> 5, lane = tid & 31;
    int g = lane >> 2, tg = lane & 3;
    int l0 = blockIdx.x * 64;
    int h  = blockIdx.y;
    int b  = blockIdx.z;

    const float* qbase = qg  + ((size_t)(b * LQ  + l0)) * HDIM + h * DH;
    const float* kbase = kvg + ((size_t)(b * LKV)) * (2 * HDIM) + h * DH;
    const float* vbase = kbase + HDIM;

    // prologue: stage Q + K/V tile 0 in one cp.async group
#pragma unroll
    for (int i = 0; i < 8; i++) {
        int idx = tid + i * 128;
        int r = idx >> 4, c4 = (idx & 15) * 4;
        CP16(&Qs[r * AP + c4], qbase + (size_t)r * HDIM + c4);
        size_t go = (size_t)r * (2 * HDIM) + c4;
        CP16(&Ks[r * AP + c4], kbase + go);
        CP16(&Vs[r * AP + c4], vbase + go);
    }
    CP_COMMIT();

    if (tid < 64) { m_s[tid] = -3.0e38f; l_s[tid] = 0.f; }

    float o[8][4] = {};
    int r0 = warp * 16;

    for (int jt = 0; jt < LKV / 64; jt++) {
        int buf = jt & 1;
        if (jt + 1 < LKV / 64) {
            int jb = (jt + 1) * 64;
            float* kd = Ks + (buf ^ 1) * (64 * AP);
            float* vd = Vs + (buf ^ 1) * (64 * AP);
#pragma unroll
            for (int i = 0; i < 8; i++) {
                int idx = tid + i * 128;
                int r = idx >> 4, c4 = (idx & 15) * 4;
                size_t go = (size_t)(jb + r) * (2 * HDIM) + c4;
                CP16(&kd[r * AP + c4], kbase + go);
                CP16(&vd[r * AP + c4], vbase + go);
            }
            CP_COMMIT();
            CP_WAIT1();
        } else {
            CP_WAIT0();
        }
        __syncthreads();

        const float* kc = Ks + buf * (64 * AP);
        const float* vc = Vs + buf * (64 * AP);

        // S = Q @ K^T  (warp: 16 rows x 64 kv-cols)
        float sfr[8][4] = {};
#pragma unroll
        for (int kk = 0; kk < 64; kk += 8) {
            unsigned a[4];
            a[0] = __float_as_uint(Qs[(r0 + g)     * AP + kk + tg]);
            a[1] = __float_as_uint(Qs[(r0 + g + 8) * AP + kk + tg]);
            a[2] = __float_as_uint(Qs[(r0 + g)     * AP + kk + tg + 4]);
            a[3] = __float_as_uint(Qs[(r0 + g + 8) * AP + kk + tg + 4]);
#pragma unroll
            for (int nt = 0; nt < 8; nt++) {
                unsigned bb[2];
                bb[0] = __float_as_uint(kc[(nt * 8 + g) * AP + kk + tg]);
                bb[1] = __float_as_uint(kc[(nt * 8 + g) * AP + kk + tg + 4]);
                mma_tf32(sfr[nt], a, bb);
            }
        }
#pragma unroll
        for (int nt = 0; nt < 8; nt++) {
            int c = nt * 8 + 2 * tg;
            Ss[(r0 + g) * AP + c]         = sfr[nt][0] * 0.125f;
            Ss[(r0 + g) * AP + c + 1]     = sfr[nt][1] * 0.125f;
            Ss[(r0 + g + 8) * AP + c]     = sfr[nt][2] * 0.125f;
            Ss[(r0 + g + 8) * AP + c + 1] = sfr[nt][3] * 0.125f;
        }
        __syncthreads();

        // online softmax: 2 threads per row
        {
            int row = tid >> 1, half = tid & 1;
            float* srow = Ss + row * AP + half * 32;
            float mx = -3.0e38f;
#pragma unroll
            for (int c2 = 0; c2 < 32; c2++) mx = fmaxf(mx, srow[c2]);
            mx = fmaxf(mx, __shfl_xor_sync(0xffffffffu, mx, 1));
            float mo = m_s[row];
            float mn = fmaxf(mo, mx);
            float sum = 0.f;
#pragma unroll
            for (int c2 = 0; c2 < 32; c2++) {
                float p = __expf(srow[c2] - mn);
                sum += p;
                ((unsigned*)srow)[c2] = f2tf(p);
            }
            sum += __shfl_xor_sync(0xffffffffu, sum, 1);
            if (half == 0) {
                float corr = __expf(mo - mn);
                c_s[row] = corr;
                m_s[row] = mn;
                l_s[row] = l_s[row] * corr + sum;
            }
        }
        __syncthreads();

        // rescale O, then O += P @ V
        float c0f = c_s[r0 + g], c1f = c_s[r0 + g + 8];
        unsigned* Ps = (unsigned*)Ss;
#pragma unroll
        for (int nt = 0; nt < 8; nt++) {
            o[nt][0] *= c0f; o[nt][1] *= c0f;
            o[nt][2] *= c1f; o[nt][3] *= c1f;
        }
#pragma unroll
        for (int kk = 0; kk < 64; kk += 8) {
            unsigned a[4];
            a[0] = Ps[(r0 + g)     * AP + kk + tg];
            a[1] = Ps[(r0 + g + 8) * AP + kk + tg];
            a[2] = Ps[(r0 + g)     * AP + kk + tg + 4];
            a[3] = Ps[(r0 + g + 8) * AP + kk + tg + 4];
#pragma unroll
            for (int nt = 0; nt < 8; nt++) {
                unsigned bb[2];
                bb[0] = __float_as_uint(vc[(kk + tg)     * AP + nt * 8 + g]);
                bb[1] = __float_as_uint(vc[(kk + tg + 4) * AP + nt * 8 + g]);
                mma_tf32(o[nt], a, bb);
            }
        }
        __syncthreads();
    }

    // finalize: O /= l, store tf32-rounded (feeds out-proj MMA)
    float inv0 = 1.f / l_s[r0 + g];
    float inv1 = 1.f / l_s[r0 + g + 8];
    float* ob = og + ((size_t)(b * LQ + l0)) * HDIM + h * DH;
#pragma unroll
    for (int nt = 0; nt < 8; nt++) {
        int c = nt * 8 + 2 * tg;
        size_t off0 = (size_t)(r0 + g) * HDIM + c;
        size_t off1 = (size_t)(r0 + g + 8) * HDIM + c;
        ob[off0]     = __uint_as_float(f2tf(o[nt][0] * inv0));
        ob[off0 + 1] = __uint_as_float(f2tf(o[nt][1] * inv0));
        ob[off1]     = __uint_as_float(f2tf(o[nt][2] * inv1));
        ob[off1 + 1] = __uint_as_float(f2tf(o[nt][3] * inv1));
    }
}

// ---------------- host launcher --------------------------------------------
extern "C" void kernel_launch(void* const* d_in, const int* in_sizes, int n_in,
                              void* d_out, int out_size)
{
    const float* x_q    = (const float*)d_in[0];
    const float* x_kv   = (const float*)d_in[1];
    const float* t_vec  = (const float*)d_in[2];
    const float* Wq     = (const float*)d_in[3];
    const float* bq     = (const float*)d_in[4];
    const float* Wkv    = (const float*)d_in[5];
    const float* bkv    = (const float*)d_in[6];
    const float* Wp     = (const float*)d_in[7];
    const float* bp     = (const float*)d_in[8];
    const float* Wss_q  = (const float*)d_in[9];
    const float* bss_q  = (const float*)d_in[10];
    const float* Wss_kv = (const float*)d_in[11];
    const float* bss_kv = (const float*)d_in[12];
    float* out = (float*)d_out;

    float *ss_q, *ss_kv, *xq_ln, *xkv_ln, *qb, *kvb, *attnb, *wq, *wkv, *wp;
    cudaGetSymbolAddress((void**)&ss_q,   g_ss_q);
    cudaGetSymbolAddress((void**)&ss_kv,  g_ss_kv);
    cudaGetSymbolAddress((void**)&xq_ln,  g_xq_ln);
    cudaGetSymbolAddress((void**)&xkv_ln, g_xkv_ln);
    cudaGetSymbolAddress((void**)&qb,     g_q);
    cudaGetSymbolAddress((void**)&kvb,    g_kv);
    cudaGetSymbolAddress((void**)&attnb,  g_attn);
    cudaGetSymbolAddress((void**)&wq,     g_wq);
    cudaGetSymbolAddress((void**)&wkv,    g_wkv);
    cudaGetSymbolAddress((void**)&wp,     g_wp);

    static bool attr_done = false;
    if (!attr_done) {
        cudaFuncSetAttribute(gemm_tf32_kernel<false, true>,
                             cudaFuncAttributeMaxDynamicSharedMemorySize, GEMM_SMEM);
        cudaFuncSetAttribute(gemm_tf32_kernel<true, false>,
                             cudaFuncAttributeMaxDynamicSharedMemorySize, GEMM_SMEM);
        cudaFuncSetAttribute(attn_kernel,
                             cudaFuncAttributeMaxDynamicSharedMemorySize, ATTN_SMEM);
        attr_done = true;
    }

    // 0) pre-round weights to tf32 bit patterns (identity under HW truncation)
    round_tf32_kernel<<<HDIM * HDIM / 1024,     256>>>(Wq,  wq);
    round_tf32_kernel<<<HDIM * 2 * HDIM / 1024, 256>>>(Wkv, wkv);
    round_tf32_kernel<<<HDIM * HDIM / 1024,     256>>>(Wp,  wp);

    // 1) adaLN scale/shift vectors
    ss_kernel<<<dim3(2 * HDIM / 256, BDIM), 256>>>(t_vec, Wss_q,  bss_q,  ss_q);
    ss_kernel<<<dim3(2 * HDIM / 256, BDIM), 256>>>(t_vec, Wss_kv, bss_kv, ss_kv);

    // 2) adaLN (tf32-rounded outputs)
    adaln_kernel<<<BDIM * LQ,  256>>>(x_q,  ss_q,  xq_ln,  LQ);
    adaln_kernel<<<BDIM * LKV, 256>>>(x_kv, ss_kv, xkv_ln, LKV);

    // 3) projections (outputs tf32-rounded for attention MMAs)
    gemm_tf32_kernel<false, true><<<dim3(HDIM / GBN, BDIM * LQ / GBM), 256, GEMM_SMEM>>>(
        xq_ln, wq, bq, nullptr, qb, BDIM * LQ, HDIM, HDIM);
    gemm_tf32_kernel<false, true><<<dim3(2 * HDIM / GBN, BDIM * LKV / GBM), 256, GEMM_SMEM>>>(
        xkv_ln, wkv, bkv, nullptr, kvb, BDIM * LKV, 2 * HDIM, HDIM);

    // 4) attention
    attn_kernel<<<dim3(LQ / 64, NH, BDIM), 128, ATTN_SMEM>>>(qb, kvb, attnb);

    // 5) output projection + residual (exact fp32 epilogue)
    gemm_tf32_kernel<true, false><<<dim3(HDIM / GBN, BDIM * LQ / GBM), 256, GEMM_SMEM>>>(
        attnb, wp, bp, x_q, out, BDIM * LQ, HDIM, HDIM);
}